// round 8
// baseline (speedup 1.0000x reference)
#include <cuda_runtime.h>
#include <cuda_bf16.h>
#include <cstdint>

#define TSTEPS 2048
#define BATCH  32
#define IDIM   512
#define HDIM   512
#define GDIM   2048   // 4*H

#define RG      128    // persistent CTAs in recurrence
#define NGRP    8      // barrier groups
#define GRPSZ   16     // CTAs per group
#define SLABST  68     // per-warp slab k-stride (floats)
#define SREDST  33     // sred b-stride
#define NBAR    (1 + TSTEPS)

#define TOTX (TSTEPS * BATCH * IDIM)   // 33,554,432
#define TOTW (GDIM * IDIM)             // 1,048,576

// ---- static device scratch (no cudaMalloc allowed) ----
__device__ float g_xpre[(size_t)TSTEPS * GDIM * BATCH];   // [t][g][b]
__device__ float g_h[2][BATCH * HDIM];                    // double-buffered h
__device__ uint4 g_xhi4[TOTX / 8], g_xlo4[TOTX / 8];      // [t][b][k] bf16
__device__ uint4 g_whi4[TOTW / 8], g_wlo4[TOTW / 8];      // [g][k]    bf16

// two-level barrier state: each counter/flag in its own 128B line
__device__ __align__(128) unsigned long long g_leaf[NGRP * 16];
__device__ __align__(128) unsigned long long g_done[NGRP * 16];

// ---- mma helpers ----
__device__ __forceinline__ void mma_tf32(float (&d)[4], const unsigned (&a)[4],
                                         unsigned b0, unsigned b1)
{
    asm("mma.sync.aligned.m16n8k8.row.col.f32.tf32.tf32.f32 "
        "{%0,%1,%2,%3}, {%4,%5,%6,%7}, {%8,%9}, {%0,%1,%2,%3};"
        : "+f"(d[0]), "+f"(d[1]), "+f"(d[2]), "+f"(d[3])
        : "r"(a[0]), "r"(a[1]), "r"(a[2]), "r"(a[3]), "r"(b0), "r"(b1));
}
__device__ __forceinline__ void mma_bf16(float (&d)[4], const unsigned (&a)[4],
                                         unsigned b0, unsigned b1)
{
    asm("mma.sync.aligned.m16n8k16.row.col.f32.bf16.bf16.f32 "
        "{%0,%1,%2,%3}, {%4,%5,%6,%7}, {%8,%9}, {%0,%1,%2,%3};"
        : "+f"(d[0]), "+f"(d[1]), "+f"(d[2]), "+f"(d[3])
        : "r"(a[0]), "r"(a[1]), "r"(a[2]), "r"(a[3]), "r"(b0), "r"(b1));
}
__device__ __forceinline__ void cpasync16(uint32_t s, const void* g)
{
    asm volatile("cp.async.cg.shared.global [%0], [%1], 16;"
                 :: "r"(s), "l"(g) : "memory");
}

// ---- barrier primitives ----
__device__ __forceinline__ unsigned long long atom_add_acqrel(unsigned long long* p)
{
    unsigned long long r;
    asm volatile("atom.acq_rel.gpu.add.u64 %0, [%1], 1;"
                 : "=l"(r) : "l"(p) : "memory");
    return r;
}
__device__ __forceinline__ void st_rel(unsigned long long* p, unsigned long long v)
{
    asm volatile("st.release.gpu.u64 [%0], %1;" :: "l"(p), "l"(v) : "memory");
}
__device__ __forceinline__ unsigned long long ld_acq(const unsigned long long* p)
{
    unsigned long long v;
    asm volatile("ld.acquire.gpu.b64 %0, [%1];" : "=l"(v) : "l"(p) : "memory");
    return v;
}

// ============================================================
// Prep: split fp32 -> bf16 hi/lo planes
// ============================================================
__global__ void __launch_bounds__(256) split_x(const float* __restrict__ x)
{
    int i = blockIdx.x * 256 + threadIdx.x;
    __nv_bfloat16* hp = (__nv_bfloat16*)g_xhi4;
    __nv_bfloat16* lp = (__nv_bfloat16*)g_xlo4;
    float v = x[i];
    __nv_bfloat16 h = __float2bfloat16(v);
    hp[i] = h;
    lp[i] = __float2bfloat16(v - __bfloat162float(h));
}
__global__ void __launch_bounds__(256) split_wi(const float* __restrict__ W)
{
    int i = blockIdx.x * 256 + threadIdx.x;
    __nv_bfloat16* hp = (__nv_bfloat16*)g_whi4;
    __nv_bfloat16* lp = (__nv_bfloat16*)g_wlo4;
    float v = W[i];
    __nv_bfloat16 h = __float2bfloat16(v);
    hp[i] = h;
    lp[i] = __float2bfloat16(v - __bfloat162float(h));
}

// ============================================================
// Phase 1 (bf16 split-MMA) — unchanged
// ============================================================
__global__ void __launch_bounds__(256, 2) p1_gemm(
    const float* __restrict__ bi, const float* __restrict__ bh)
{
    __shared__ __align__(16) unsigned sw[2][128 * 36];
    __shared__ __align__(16) unsigned sx[2][32 * 36];

    const int t     = blockIdx.y;
    const int gbase = blockIdx.x * 128;
    const int tid   = threadIdx.x;
    const int wid   = tid >> 5;
    const int lane  = tid & 31;
    const int g     = lane >> 2;
    const int t4    = lane & 3;

    float acc[4][4];
    #pragma unroll
    for (int nt = 0; nt < 4; nt++)
        #pragma unroll
        for (int i = 0; i < 4; i++) acc[nt][i] = 0.f;

    const uint4* xsrc_h = g_xhi4 + ((size_t)t * BATCH * IDIM) / 8;
    const uint4* xsrc_l = g_xlo4 + ((size_t)t * BATCH * IDIM) / 8;

    for (int kb = 0; kb < IDIM; kb += 64) {
        __syncthreads();
        #pragma unroll
        for (int r = 0; r < 4; r++) {
            int ch  = r * 256 + tid;
            int row = ch >> 3, c8 = ch & 7;
            size_t src = ((size_t)(gbase + row) * IDIM + kb) / 8 + c8;
            ((uint4*)sw[0])[row * 9 + c8] = g_whi4[src];
            ((uint4*)sw[1])[row * 9 + c8] = g_wlo4[src];
        }
        {
            int row = tid >> 3, c8 = tid & 7;
            size_t src = ((size_t)row * IDIM + kb) / 8 + c8;
            ((uint4*)sx[0])[row * 9 + c8] = xsrc_h[src];
            ((uint4*)sx[1])[row * 9 + c8] = xsrc_l[src];
        }
        __syncthreads();

        #pragma unroll
        for (int c = 0; c < 4; c++) {
            const int aw = (wid * 16 + g) * 36 + c * 8 + t4;
            unsigned ahi[4], alo[4];
            ahi[0] = sw[0][aw];            ahi[1] = sw[0][aw + 8 * 36];
            ahi[2] = sw[0][aw + 4];        ahi[3] = sw[0][aw + 8 * 36 + 4];
            alo[0] = sw[1][aw];            alo[1] = sw[1][aw + 8 * 36];
            alo[2] = sw[1][aw + 4];        alo[3] = sw[1][aw + 8 * 36 + 4];
            #pragma unroll
            for (int nt = 0; nt < 4; nt++) {
                const int bw = (nt * 8 + g) * 36 + c * 8 + t4;
                unsigned bh0 = sx[0][bw], bh1 = sx[0][bw + 4];
                unsigned bl0 = sx[1][bw], bl1 = sx[1][bw + 4];
                mma_bf16(acc[nt], ahi, bh0, bh1);
                mma_bf16(acc[nt], alo, bh0, bh1);
                mma_bf16(acc[nt], ahi, bl0, bl1);
            }
        }
    }

    const int grow0 = gbase + wid * 16 + g;
    const int grow1 = grow0 + 8;
    const float bb0 = __ldg(bi + grow0) + __ldg(bh + grow0);
    const float bb1 = __ldg(bi + grow1) + __ldg(bh + grow1);
    float* op = g_xpre + (size_t)t * GDIM * BATCH;
    #pragma unroll
    for (int nt = 0; nt < 4; nt++) {
        int b = nt * 8 + 2 * t4;
        *(float2*)(op + (size_t)grow0 * BATCH + b) =
            make_float2(acc[nt][0] + bb0, acc[nt][1] + bb0);
        *(float2*)(op + (size_t)grow1 * BATCH + b) =
            make_float2(acc[nt][2] + bb1, acc[nt][3] + bb1);
    }
}

// ============================================================
// Phase 2: persistent recurrence, split-tf32 MMA,
// two-level contention-free grid barrier.
// ============================================================
extern __shared__ __align__(16) float dsm[];   // 8 slabs of [32][SLABST]

__global__ void __launch_bounds__(256) lstm_rec(
    const float* __restrict__ Wh, float* __restrict__ out)
{
    __shared__ float sred[8 * 16 * SREDST];
    __shared__ float houts[32][4];

    const int tid  = threadIdx.x;
    const int cta  = blockIdx.x;
    const int j0   = cta * 4;
    const int warp = tid >> 5;
    const int lane = tid & 31;
    const int gid  = lane >> 2;
    const int tid4 = lane & 3;
    const int grp  = cta >> 4;            // barrier group

    float* slab = dsm + warp * 32 * SLABST;
    uint32_t slab_s = (uint32_t)__cvta_generic_to_shared(slab);

    // ---- barrier bases (monotone counters; floor to run base) ----
    unsigned long long leaf_base = 0, dgrp_base = 0, dpoll_base = 0;
    if (tid == 0) {
        unsigned long long lv = ld_acq(&g_leaf[grp * 16]);
        unsigned long long per = (unsigned long long)NBAR * GRPSZ;
        leaf_base = (lv / per) * per;
        unsigned long long dv = ld_acq(&g_done[grp * 16]);
        dgrp_base = (dv / NBAR) * (unsigned long long)NBAR;
    }
    if (warp == 0 && lane < NGRP) {
        unsigned long long dv = ld_acq(&g_done[lane * 16]);
        dpoll_base = (dv / NBAR) * (unsigned long long)NBAR;
    }

    // preload Wh A-fragments, split tf32 hi/lo in registers
    unsigned whi[8][4], wlo[8][4];
    {
        const int r0 = gid, r1 = gid + 8;
        const int grow0 = (r0 >> 2) * HDIM + j0 + (r0 & 3);
        const int grow1 = (r1 >> 2) * HDIM + j0 + (r1 & 3);
        const int kbase = warp * 64;
        #pragma unroll
        for (int c = 0; c < 8; c++) {
            int k0 = kbase + c * 8 + tid4;
            float a[4];
            a[0] = Wh[(size_t)grow0 * HDIM + k0];
            a[1] = Wh[(size_t)grow1 * HDIM + k0];
            a[2] = Wh[(size_t)grow0 * HDIM + k0 + 4];
            a[3] = Wh[(size_t)grow1 * HDIM + k0 + 4];
            #pragma unroll
            for (int i = 0; i < 4; i++) {
                unsigned hb = __float_as_uint(a[i]) & 0xFFFFE000u;
                whi[c][i] = hb;
                wlo[c][i] = __float_as_uint(a[i] - __uint_as_float(hb));
            }
        }
    }

    const int ub  = tid & 31;
    const int ujl = tid >> 5;
    float creg = 0.f;
    if (tid < 128) g_h[0][ub * HDIM + j0 + ujl] = 0.f;

    int bar = 0;

    // ---- initial barrier: h buffer 0 visible everywhere ----
    __syncthreads();
    ++bar;
    if (tid == 0) {
        unsigned long long lv = atom_add_acqrel(&g_leaf[grp * 16]);
        if (lv == leaf_base + (unsigned long long)bar * GRPSZ - 1)
            st_rel(&g_done[grp * 16], dgrp_base + (unsigned long long)bar);
    }
    if (warp == 0) {
        bool ok;
        do {
            bool mine = true;
            if (lane < NGRP)
                mine = (ld_acq(&g_done[lane * 16]) >=
                        dpoll_base + (unsigned long long)bar);
            ok = __all_sync(0xFFFFFFFFu, mine);
        } while (!ok);
    }
    __syncthreads();

    // prefetch x_pre for t=0
    float xq[4];
    if (tid < 128) {
        #pragma unroll
        for (int q = 0; q < 4; q++)
            xq[q] = __ldg(g_xpre + ((size_t)q * HDIM + j0 + ujl) * BATCH + ub);
    }

    const int krow = lane >> 4;        // 0/1
    const int kc   = lane & 15;        // 16B chunk
    const uint32_t sdst0 = slab_s + (uint32_t)(krow * SLABST + kc * 4) * 4u;

    for (int t = 0; t < TSTEPS; t++) {
        const int p = t & 1;

        // per-warp slab stage: h[b][warp*64 .. +64), no CTA sync
        {
            const float* gsrc = g_h[p] + (size_t)krow * HDIM + warp * 64 + kc * 4;
            #pragma unroll
            for (int i = 0; i < 16; i++)
                cpasync16(sdst0 + (uint32_t)(i * 2 * SLABST) * 4u,
                          gsrc + (size_t)i * 2 * HDIM);
            asm volatile("cp.async.commit_group;");
            asm volatile("cp.async.wait_group 0;" ::: "memory");
            __syncwarp();
        }

        // tensor-core matvec on own slab
        float acc[4][4];
        #pragma unroll
        for (int nt = 0; nt < 4; nt++)
            #pragma unroll
            for (int i = 0; i < 4; i++) acc[nt][i] = 0.f;

        #pragma unroll
        for (int c = 0; c < 8; c++) {
            #pragma unroll
            for (int nt = 0; nt < 4; nt++) {
                int b = nt * 8 + gid;
                float f0 = slab[b * SLABST + c * 8 + tid4];
                float f1 = slab[b * SLABST + c * 8 + tid4 + 4];
                unsigned bh0 = __float_as_uint(f0) & 0xFFFFE000u;
                unsigned bh1 = __float_as_uint(f1) & 0xFFFFE000u;
                unsigned bl0 = __float_as_uint(f0 - __uint_as_float(bh0));
                unsigned bl1 = __float_as_uint(f1 - __uint_as_float(bh1));
                mma_tf32(acc[nt], whi[c], bh0, bh1);
                mma_tf32(acc[nt], wlo[c], bh0, bh1);
                mma_tf32(acc[nt], whi[c], bl0, bl1);
            }
        }

        // spill partials
        {
            float* sr = sred + warp * 16 * SREDST;
            #pragma unroll
            for (int nt = 0; nt < 4; nt++) {
                int bb = nt * 8 + 2 * tid4;
                sr[gid * SREDST + bb]           = acc[nt][0];
                sr[gid * SREDST + bb + 1]       = acc[nt][1];
                sr[(gid + 8) * SREDST + bb]     = acc[nt][2];
                sr[(gid + 8) * SREDST + bb + 1] = acc[nt][3];
            }
        }
        __syncthreads();

        // reduce + activation + cell update
        if (tid < 128) {
            float pre[4];
            #pragma unroll
            for (int q = 0; q < 4; q++) {
                int rr = q * 4 + ujl;
                float v0 = sred[(0 * 16 + rr) * SREDST + ub];
                float v1 = sred[(1 * 16 + rr) * SREDST + ub];
                float v2 = sred[(2 * 16 + rr) * SREDST + ub];
                float v3 = sred[(3 * 16 + rr) * SREDST + ub];
                float v4 = sred[(4 * 16 + rr) * SREDST + ub];
                float v5 = sred[(5 * 16 + rr) * SREDST + ub];
                float v6 = sred[(6 * 16 + rr) * SREDST + ub];
                float v7 = sred[(7 * 16 + rr) * SREDST + ub];
                pre[q] = ((v0 + v1) + (v2 + v3)) + ((v4 + v5) + (v6 + v7)) + xq[q];
            }
            float ig = 1.f / (1.f + __expf(-pre[0]));
            float fg = 1.f / (1.f + __expf(-pre[1]));
            float og = 1.f / (1.f + __expf(-pre[2]));
            float gt = tanhf(pre[3]);
            creg = creg * fg + ig * gt;
            float hn = og * tanhf(creg);
            g_h[p ^ 1][ub * HDIM + j0 + ujl] = hn;
            houts[ub][ujl] = hn;
            if (t == TSTEPS - 1) {
                size_t o2 = (size_t)TSTEPS * BATCH * HDIM;
                out[o2 + ub * HDIM + j0 + ujl] = hn;
                out[o2 + BATCH * HDIM + ub * HDIM + j0 + ujl] = creg;
            }
        }
        __syncthreads();                 // h stores + houts visible CTA-wide

        // ---- arrive (leaf RMW, group-local line; 16th arriver publishes)
        ++bar;
        if (tid == 0) {
            unsigned long long lv = atom_add_acqrel(&g_leaf[grp * 16]);
            if (lv == leaf_base + (unsigned long long)bar * GRPSZ - 1)
                st_rel(&g_done[grp * 16], dgrp_base + (unsigned long long)bar);
        }

        // window work: output write for step t + x_pre prefetch for t+1
        if (tid < 32)
            *(float4*)(out + ((size_t)t * BATCH + tid) * HDIM + j0) =
                *(const float4*)houts[tid];
        {
            int tn = (t + 1 < TSTEPS) ? t + 1 : t;
            if (tid < 128) {
                #pragma unroll
                for (int q = 0; q < 4; q++)
                    xq[q] = __ldg(g_xpre + ((size_t)tn * GDIM + q * HDIM + j0 + ujl) * BATCH + ub);
            }
        }

        // ---- spin on read-only done flags (8 lines, no RMW interference)
        if (warp == 0) {
            bool ok;
            do {
                bool mine = true;
                if (lane < NGRP)
                    mine = (ld_acq(&g_done[lane * 16]) >=
                            dpoll_base + (unsigned long long)bar);
                ok = __all_sync(0xFFFFFFFFu, mine);
            } while (!ok);
        }
        __syncthreads();
    }
}

// ============================================================
extern "C" void kernel_launch(void* const* d_in, const int* in_sizes, int n_in,
                              void* d_out, int out_size)
{
    const float* x  = (const float*)d_in[0];
    const float* Wi = (const float*)d_in[1];
    const float* bi = (const float*)d_in[2];
    const float* Wh = (const float*)d_in[3];
    const float* bh = (const float*)d_in[4];
    float* out = (float*)d_out;

    size_t rec_smem = (size_t)(8 * 32 * SLABST) * sizeof(float); // 69632 B
    cudaFuncSetAttribute(lstm_rec, cudaFuncAttributeMaxDynamicSharedMemorySize,
                         (int)rec_smem);

    split_x<<<TOTX / 256, 256>>>(x);
    split_wi<<<TOTW / 256, 256>>>(Wi);
    dim3 g1(GDIM / 128, TSTEPS);
    p1_gemm<<<g1, 256>>>(bi, bh);
    lstm_rec<<<RG, 256, rec_smem>>>(Wh, out);
}

// round 9
// speedup vs baseline: 1.5920x; 1.5920x over previous
#include <cuda_runtime.h>
#include <cuda_bf16.h>
#include <cstdint>

#define TSTEPS 2048
#define BATCH  32
#define IDIM   512
#define HDIM   512
#define GDIM   2048   // 4*H

#define RG      128    // persistent CTAs in recurrence
#define SLABST  264    // slab b-row stride in words (256 + 8)
#define NBAR    (1 + TSTEPS)

#define TOTX (TSTEPS * BATCH * IDIM)   // 33,554,432
#define TOTW (GDIM * IDIM)             // 1,048,576

// ---- static device scratch (no cudaMalloc allowed) ----
__device__ float g_xpre[(size_t)TSTEPS * GDIM * BATCH];   // [t][g][b]
__device__ float g_h[2][BATCH * HDIM];                    // double-buffered h
__device__ unsigned long long g_cnt;                      // grid barrier counter
__device__ uint4 g_xhi4[TOTX / 8], g_xlo4[TOTX / 8];      // [t][b][k] bf16
__device__ uint4 g_whi4[TOTW / 8], g_wlo4[TOTW / 8];      // [g][k]    bf16

// ---- mma helper ----
__device__ __forceinline__ void mma_bf16(float (&d)[4], const unsigned (&a)[4],
                                         unsigned b0, unsigned b1)
{
    asm("mma.sync.aligned.m16n8k16.row.col.f32.bf16.bf16.f32 "
        "{%0,%1,%2,%3}, {%4,%5,%6,%7}, {%8,%9}, {%0,%1,%2,%3};"
        : "+f"(d[0]), "+f"(d[1]), "+f"(d[2]), "+f"(d[3])
        : "r"(a[0]), "r"(a[1]), "r"(a[2]), "r"(a[3]), "r"(b0), "r"(b1));
}
__device__ __forceinline__ void cpasync16(uint32_t s, const void* g)
{
    asm volatile("cp.async.cg.shared.global [%0], [%1], 16;"
                 :: "r"(s), "l"(g) : "memory");
}
// pack (f0 -> low bf16, f1 -> high bf16), hi plane + exact-ish residual lo plane
__device__ __forceinline__ void bsplit(float f0, float f1,
                                       unsigned& hp, unsigned& lp)
{
    asm("cvt.rn.bf16x2.f32 %0, %1, %2;" : "=r"(hp) : "f"(f1), "f"(f0));
    float h0 = __uint_as_float(hp << 16);
    float h1 = __uint_as_float(hp & 0xFFFF0000u);
    float r0 = f0 - h0, r1 = f1 - h1;
    asm("cvt.rn.bf16x2.f32 %0, %1, %2;" : "=r"(lp) : "f"(r1), "f"(r0));
}

// ---- flat barrier primitives (R6, best measured) ----
__device__ __forceinline__ void gbar_arrive()
{
    unsigned long long* p = &g_cnt;
    asm volatile("red.release.gpu.add.u64 [%0], %1;"
                 :: "l"(p), "l"(1ULL) : "memory");
}
__device__ __forceinline__ void gbar_spin(unsigned long long target)
{
    unsigned long long* p = &g_cnt;
    unsigned long long v;
    do {
        asm volatile("ld.acquire.gpu.b64 %0, [%1];"
                     : "=l"(v) : "l"(p) : "memory");
    } while (v < target);
}

// ============================================================
// Prep: split fp32 -> bf16 hi/lo planes
// ============================================================
__global__ void __launch_bounds__(256) split_x(const float* __restrict__ x)
{
    int i = blockIdx.x * 256 + threadIdx.x;
    __nv_bfloat16* hp = (__nv_bfloat16*)g_xhi4;
    __nv_bfloat16* lp = (__nv_bfloat16*)g_xlo4;
    float v = x[i];
    __nv_bfloat16 h = __float2bfloat16(v);
    hp[i] = h;
    lp[i] = __float2bfloat16(v - __bfloat162float(h));
}
__global__ void __launch_bounds__(256) split_wi(const float* __restrict__ W)
{
    int i = blockIdx.x * 256 + threadIdx.x;
    __nv_bfloat16* hp = (__nv_bfloat16*)g_whi4;
    __nv_bfloat16* lp = (__nv_bfloat16*)g_wlo4;
    float v = W[i];
    __nv_bfloat16 h = __float2bfloat16(v);
    hp[i] = h;
    lp[i] = __float2bfloat16(v - __bfloat162float(h));
}

// ============================================================
// Phase 1 (bf16 split-MMA) — unchanged
// ============================================================
__global__ void __launch_bounds__(256, 2) p1_gemm(
    const float* __restrict__ bi, const float* __restrict__ bh)
{
    __shared__ __align__(16) unsigned sw[2][128 * 36];
    __shared__ __align__(16) unsigned sx[2][32 * 36];

    const int t     = blockIdx.y;
    const int gbase = blockIdx.x * 128;
    const int tid   = threadIdx.x;
    const int wid   = tid >> 5;
    const int lane  = tid & 31;
    const int g     = lane >> 2;
    const int t4    = lane & 3;

    float acc[4][4];
    #pragma unroll
    for (int nt = 0; nt < 4; nt++)
        #pragma unroll
        for (int i = 0; i < 4; i++) acc[nt][i] = 0.f;

    const uint4* xsrc_h = g_xhi4 + ((size_t)t * BATCH * IDIM) / 8;
    const uint4* xsrc_l = g_xlo4 + ((size_t)t * BATCH * IDIM) / 8;

    for (int kb = 0; kb < IDIM; kb += 64) {
        __syncthreads();
        #pragma unroll
        for (int r = 0; r < 4; r++) {
            int ch  = r * 256 + tid;
            int row = ch >> 3, c8 = ch & 7;
            size_t src = ((size_t)(gbase + row) * IDIM + kb) / 8 + c8;
            ((uint4*)sw[0])[row * 9 + c8] = g_whi4[src];
            ((uint4*)sw[1])[row * 9 + c8] = g_wlo4[src];
        }
        {
            int row = tid >> 3, c8 = tid & 7;
            size_t src = ((size_t)row * IDIM + kb) / 8 + c8;
            ((uint4*)sx[0])[row * 9 + c8] = xsrc_h[src];
            ((uint4*)sx[1])[row * 9 + c8] = xsrc_l[src];
        }
        __syncthreads();

        #pragma unroll
        for (int c = 0; c < 4; c++) {
            const int aw = (wid * 16 + g) * 36 + c * 8 + t4;
            unsigned ahi[4], alo[4];
            ahi[0] = sw[0][aw];            ahi[1] = sw[0][aw + 8 * 36];
            ahi[2] = sw[0][aw + 4];        ahi[3] = sw[0][aw + 8 * 36 + 4];
            alo[0] = sw[1][aw];            alo[1] = sw[1][aw + 8 * 36];
            alo[2] = sw[1][aw + 4];        alo[3] = sw[1][aw + 8 * 36 + 4];
            #pragma unroll
            for (int nt = 0; nt < 4; nt++) {
                const int bw = (nt * 8 + g) * 36 + c * 8 + t4;
                unsigned bh0 = sx[0][bw], bh1 = sx[0][bw + 4];
                unsigned bl0 = sx[1][bw], bl1 = sx[1][bw + 4];
                mma_bf16(acc[nt], ahi, bh0, bh1);
                mma_bf16(acc[nt], alo, bh0, bh1);
                mma_bf16(acc[nt], ahi, bl0, bl1);
            }
        }
    }

    const int grow0 = gbase + wid * 16 + g;
    const int grow1 = grow0 + 8;
    const float bb0 = __ldg(bi + grow0) + __ldg(bh + grow0);
    const float bb1 = __ldg(bi + grow1) + __ldg(bh + grow1);
    float* op = g_xpre + (size_t)t * GDIM * BATCH;
    #pragma unroll
    for (int nt = 0; nt < 4; nt++) {
        int b = nt * 8 + 2 * t4;
        *(float2*)(op + (size_t)grow0 * BATCH + b) =
            make_float2(acc[nt][0] + bb0, acc[nt][1] + bb0);
        *(float2*)(op + (size_t)grow1 * BATCH + b) =
            make_float2(acc[nt][2] + bb1, acc[nt][3] + bb1);
    }
}

// ============================================================
// Phase 2: persistent recurrence. CTA = 16 h-cols x 8 batches
// (64 gate rows). Stage only h[8b][512] = 16 KB/step.
// Warp (mt, kh): gates of type mt for 16 j, k-half kh.
// Weights pre-split bf16-packed in registers (128 regs).
// ============================================================
__global__ void __launch_bounds__(256) lstm_rec(
    const float* __restrict__ Wh, float* __restrict__ out)
{
    __shared__ __align__(16) float slab[2][8][SLABST]; // [kh][b][k+pad]
    __shared__ float sred[4][2][16][10];               // [q][kh][j][b pad]
    __shared__ float houts[8][16];                     // [b][j]
    __shared__ unsigned long long sbase;

    const int tid  = threadIdx.x;
    const int cta  = blockIdx.x;
    const int jb   = cta >> 2;             // 0..31
    const int bb   = cta & 3;              // 0..3
    const int j0   = jb * 16;
    const int b0   = bb * 8;
    const int warp = tid >> 5;
    const int lane = tid & 31;
    const int gid  = lane >> 2;            // 0..7
    const int t4   = lane & 3;             // 0..3
    const int mt   = warp & 3;             // gate type
    const int kh   = warp >> 2;            // k-half

    // ---- preload Wh fragments (bf16 hi/lo packed, registers) ----
    unsigned ahi[16][4], alo[16][4];
    {
        const int r0 = mt * HDIM + j0 + gid;      // global gate rows
        const int r1 = r0 + 8;
        #pragma unroll
        for (int c = 0; c < 16; c++) {
            int kb = kh * 256 + c * 16 + 2 * t4;
            float a00 = Wh[(size_t)r0 * HDIM + kb];
            float a01 = Wh[(size_t)r0 * HDIM + kb + 1];
            float a10 = Wh[(size_t)r1 * HDIM + kb];
            float a11 = Wh[(size_t)r1 * HDIM + kb + 1];
            float a20 = Wh[(size_t)r0 * HDIM + kb + 8];
            float a21 = Wh[(size_t)r0 * HDIM + kb + 9];
            float a30 = Wh[(size_t)r1 * HDIM + kb + 8];
            float a31 = Wh[(size_t)r1 * HDIM + kb + 9];
            bsplit(a00, a01, ahi[c][0], alo[c][0]);
            bsplit(a10, a11, ahi[c][1], alo[c][1]);
            bsplit(a20, a21, ahi[c][2], alo[c][2]);
            bsplit(a30, a31, ahi[c][3], alo[c][3]);
        }
    }

    // cell ownership: threads 0..127 own (j = tid>>3, b = tid&7)
    const int uj = tid >> 3;   // 0..15
    const int ub = tid & 7;    // 0..7
    float creg = 0.f;
    if (tid < 128) g_h[0][(b0 + ub) * HDIM + j0 + uj] = 0.f;

    if (tid == 0) {
        unsigned long long v;
        asm volatile("ld.acquire.gpu.b64 %0, [%1];"
                     : "=l"(v) : "l"(&g_cnt) : "memory");
        unsigned long long per = (unsigned long long)NBAR * RG;
        sbase = (v / per) * per;
    }
    __syncthreads();
    const unsigned long long base = sbase;
    int bar = 0;

    // initial barrier: h buffer 0 visible everywhere
    __syncthreads();
    ++bar;
    if (tid == 0) { gbar_arrive(); gbar_spin(base + (unsigned long long)bar * RG); }
    __syncthreads();

    // prefetch x_pre for t=0
    float xq[4];
    if (tid < 128) {
        #pragma unroll
        for (int q = 0; q < 4; q++)
            xq[q] = __ldg(g_xpre + ((size_t)q * HDIM + j0 + uj) * BATCH + b0 + ub);
    }

    // staging roles: warp stages rows r = 2*warp + (lane>>4)
    const int srow = 2 * warp + (lane >> 4);
    const int skh  = srow >> 3;
    const int sb   = srow & 7;
    const int sc0  = lane & 15;              // chunk base
    uint32_t sdst0 = (uint32_t)__cvta_generic_to_shared(
                        &slab[skh][sb][sc0 * 4]);

    for (int t = 0; t < TSTEPS; t++) {
        const int p = t & 1;

        // ---- stage h[8b][512] : 16 KB via cp.async ----
        {
            const float* gsrc = g_h[p] + (size_t)(b0 + sb) * HDIM
                                + skh * 256 + sc0 * 4;
            #pragma unroll
            for (int i = 0; i < 4; i++)
                cpasync16(sdst0 + (uint32_t)(i * 16) * 4u * 4u,
                          gsrc + i * 64);
            asm volatile("cp.async.commit_group;");
            asm volatile("cp.async.wait_group 0;" ::: "memory");
        }
        __syncthreads();

        // ---- MMA: 16 chunks x 3 passes, 3 independent acc chains ----
        float accA[4], accB[4], accC[4];
        #pragma unroll
        for (int i = 0; i < 4; i++) { accA[i] = 0.f; accB[i] = 0.f; accC[i] = 0.f; }

        const float* sl = &slab[kh][0][0];
        #pragma unroll
        for (int c = 0; c < 16; c++) {
            int w0 = gid * SLABST + c * 16 + 2 * t4;
            float2 f0 = *(const float2*)(sl + w0);       // k pair at 2t4
            float2 f1 = *(const float2*)(sl + w0 + 8);   // k pair at 2t4+8
            unsigned bh0, bl0, bh1, bl1;
            bsplit(f0.x, f0.y, bh0, bl0);
            bsplit(f1.x, f1.y, bh1, bl1);
            mma_bf16(accA, ahi[c], bh0, bh1);
            mma_bf16(accB, alo[c], bh0, bh1);
            mma_bf16(accC, ahi[c], bl0, bl1);
        }

        // ---- spill (STS.64): rows (gid, gid+8), cols (2t4, 2t4+1) ----
        {
            float d0 = accA[0] + accB[0] + accC[0];
            float d1 = accA[1] + accB[1] + accC[1];
            float d2 = accA[2] + accB[2] + accC[2];
            float d3 = accA[3] + accB[3] + accC[3];
            *(float2*)&sred[mt][kh][gid][2 * t4]     = make_float2(d0, d1);
            *(float2*)&sred[mt][kh][gid + 8][2 * t4] = make_float2(d2, d3);
        }
        __syncthreads();

        // ---- reduce (2-way) + activation + cell update ----
        if (tid < 128) {
            float pre[4];
            #pragma unroll
            for (int q = 0; q < 4; q++)
                pre[q] = xq[q] + sred[q][0][uj][ub] + sred[q][1][uj][ub];
            float ig = 1.f / (1.f + __expf(-pre[0]));
            float fg = 1.f / (1.f + __expf(-pre[1]));
            float og = 1.f / (1.f + __expf(-pre[2]));
            float gt = tanhf(pre[3]);
            creg = creg * fg + ig * gt;
            float hn = og * tanhf(creg);
            g_h[p ^ 1][(b0 + ub) * HDIM + j0 + uj] = hn;
            houts[ub][uj] = hn;
            if (t == TSTEPS - 1) {
                size_t o2 = (size_t)TSTEPS * BATCH * HDIM;
                out[o2 + (b0 + ub) * HDIM + j0 + uj] = hn;
                out[o2 + BATCH * HDIM + (b0 + ub) * HDIM + j0 + uj] = creg;
            }
        }
        __syncthreads();                 // h stores + houts done CTA-wide

        // ---- arrive, window work, spin ----
        ++bar;
        if (tid == 0) gbar_arrive();

        if (tid < 32) {                  // output write for step t
            int ob = tid >> 2, jc = tid & 3;
            *(float4*)(out + ((size_t)t * BATCH + b0 + ob) * HDIM + j0 + jc * 4) =
                *(const float4*)&houts[ob][jc * 4];
        }
        {                                // prefetch x_pre for t+1
            int tn = (t + 1 < TSTEPS) ? t + 1 : t;
            if (tid < 128) {
                #pragma unroll
                for (int q = 0; q < 4; q++)
                    xq[q] = __ldg(g_xpre + ((size_t)tn * GDIM + q * HDIM + j0 + uj) * BATCH + b0 + ub);
            }
        }

        if (tid == 0) gbar_spin(base + (unsigned long long)bar * RG);
        __syncthreads();
    }
}

// ============================================================
extern "C" void kernel_launch(void* const* d_in, const int* in_sizes, int n_in,
                              void* d_out, int out_size)
{
    const float* x  = (const float*)d_in[0];
    const float* Wi = (const float*)d_in[1];
    const float* bi = (const float*)d_in[2];
    const float* Wh = (const float*)d_in[3];
    const float* bh = (const float*)d_in[4];
    float* out = (float*)d_out;

    split_x<<<TOTX / 256, 256>>>(x);
    split_wi<<<TOTW / 256, 256>>>(Wi);
    dim3 g1(GDIM / 128, TSTEPS);
    p1_gemm<<<g1, 256>>>(bi, bh);
    lstm_rec<<<RG, 256>>>(Wh, out);
}